// round 12
// baseline (speedup 1.0000x reference)
#include <cuda_runtime.h>
#include <cuda_fp16.h>
#include <cstdint>

#define T_LEN   4096
#define D_DIM   256
#define ATT     50
#define NPAD    64
#define CH      64      // rows per chunk
#define XS      264     // x row stride (floats): conflict-free LDS.64 A loads
#define WS2     72      // W half2 row stride: conflict-free B loads
#define NBATCH  64
#define NCHUNK  (NBATCH * (T_LEN / CH))   // 4096
#define GRID    152     // GB300: 152 SMs -> exactly one wave at 1 CTA/SM
#define EPS     1e-7f

__device__ float   g_denom[NBATCH];
__device__ __half2 g_Wh2[128 * WS2];   // fp16 W^T pairs along k, zero-padded n>=ATT
__device__ float   g_up[NPAD];
__device__ float   g_bp[NPAD];

__device__ __forceinline__ float tanh_fast(float v) {
    float r;
    asm("tanh.approx.f32 %0, %1;" : "=f"(r) : "f"(v));
    return r;
}
__device__ __forceinline__ uint32_t h2u(__half2 h) {
    return *reinterpret_cast<uint32_t*>(&h);
}

__global__ void prep_kernel(const float* __restrict__ W,
                            const float* __restrict__ b,
                            const float* __restrict__ u,
                            float* __restrict__ out) {
    int i = blockIdx.x * blockDim.x + threadIdx.x;
    if (i < 128 * 64) {
        int k2 = i >> 6, n = i & 63;
        float w0 = (n < ATT) ? W[(2 * k2)     * ATT + n] : 0.0f;
        float w1 = (n < ATT) ? W[(2 * k2 + 1) * ATT + n] : 0.0f;
        g_Wh2[k2 * WS2 + n] = __floats2half2_rn(w0, w1);
    }
    if (i < NPAD) {
        g_up[i] = (i < ATT) ? u[i] : 0.0f;
        g_bp[i] = (i < ATT) ? b[i] : 0.0f;
    }
    if (i < NBATCH) g_denom[i] = 0.0f;
    if (i < NBATCH * D_DIM) out[i] = 0.0f;
}

// Phase-2 worker: NT n-tiles starting at column cbase. (identical to the 76.3us kernel)
template<int NT>
__device__ __forceinline__ void phase2(const float* __restrict__ cur,
                                       const __half2* __restrict__ Wh,
                                       const float* __restrict__ us,
                                       const float* __restrict__ bs,
                                       float* __restrict__ pp,
                                       int mrow, int cbase, int g, int t) {
    float c[NT][4];
    #pragma unroll
    for (int nt = 0; nt < NT; nt++) {
        c[nt][0] = 0.f; c[nt][1] = 0.f; c[nt][2] = 0.f; c[nt][3] = 0.f;
    }
    const float* xr0 = cur + (mrow + g) * XS;
    const float* xr1 = xr0 + 8 * XS;

    #pragma unroll 4
    for (int k0 = 0; k0 < D_DIM; k0 += 16) {
        float2 f0 = *(const float2*)&xr0[k0 + 2 * t];
        float2 f1 = *(const float2*)&xr1[k0 + 2 * t];
        float2 f2 = *(const float2*)&xr0[k0 + 2 * t + 8];
        float2 f3 = *(const float2*)&xr1[k0 + 2 * t + 8];
        uint32_t a0 = h2u(__floats2half2_rn(f0.x, f0.y));
        uint32_t a1 = h2u(__floats2half2_rn(f1.x, f1.y));
        uint32_t a2 = h2u(__floats2half2_rn(f2.x, f2.y));
        uint32_t a3 = h2u(__floats2half2_rn(f3.x, f3.y));
        const __half2* wk0 = Wh + ((k0 >> 1) + t) * WS2 + cbase;
        const __half2* wk1 = wk0 + 4 * WS2;
        #pragma unroll
        for (int nt = 0; nt < NT; nt++) {
            uint32_t b0 = h2u(wk0[nt * 8 + g]);
            uint32_t b1 = h2u(wk1[nt * 8 + g]);
            asm volatile(
                "mma.sync.aligned.m16n8k16.row.col.f32.f16.f16.f32 "
                "{%0,%1,%2,%3}, {%4,%5,%6,%7}, {%8,%9}, {%0,%1,%2,%3};"
                : "+f"(c[nt][0]), "+f"(c[nt][1]), "+f"(c[nt][2]), "+f"(c[nt][3])
                : "r"(a0), "r"(a1), "r"(a2), "r"(a3), "r"(b0), "r"(b1));
        }
    }

    float slo = 0.f, shi = 0.f;
    #pragma unroll
    for (int nt = 0; nt < NT; nt++) {
        int col = cbase + nt * 8 + 2 * t;
        float u0 = us[col], u1 = us[col + 1];
        float B0 = bs[col], B1 = bs[col + 1];
        slo += tanh_fast(c[nt][0] + B0) * u0 + tanh_fast(c[nt][1] + B1) * u1;
        shi += tanh_fast(c[nt][2] + B0) * u0 + tanh_fast(c[nt][3] + B1) * u1;
    }
    slo += __shfl_xor_sync(0xFFFFFFFFu, slo, 1);
    slo += __shfl_xor_sync(0xFFFFFFFFu, slo, 2);
    shi += __shfl_xor_sync(0xFFFFFFFFu, shi, 1);
    shi += __shfl_xor_sync(0xFFFFFFFFu, shi, 2);
    if (t == 0) {
        pp[mrow + g]     = slo;
        pp[mrow + g + 8] = shi;
    }
}

__global__ __launch_bounds__(256, 1)
void att_main_kernel(const float* __restrict__ x, float* __restrict__ out) {
    extern __shared__ float sm[];
    float*   xs  = sm;                              // 2 * CH * XS floats
    __half2* Wh  = (__half2*)(sm + 2 * CH * XS);    // 128 * WS2 half2
    float*   us  = (float*)(Wh + 128 * WS2);        // NPAD
    float*   bs  = us + NPAD;                       // NPAD
    float*   es  = bs + NPAD;                       // CH
    float*   p0  = es + CH;                         // CH
    float*   p1  = p0 + CH;                         // CH

    const int tid = threadIdx.x;

    // ---- Stage fp16 W + vectors (once per CTA) ----
    #pragma unroll
    for (int i = tid; i < 128 * WS2 / 4; i += 256)
        ((float4*)Wh)[i] = ((const float4*)g_Wh2)[i];
    if (tid < NPAD) { us[tid] = g_up[tid]; bs[tid] = g_bp[tid]; }

    const int lane = tid & 31;
    const int warp = tid >> 5;
    const int g = lane >> 2;
    const int t = lane & 3;
    const int mrow = (warp & 3) * 16;

    auto prefetch = [&](int c, int bufidx) {
        const float* xg = x + ((size_t)(c >> 6) * T_LEN + (size_t)(c & 63) * CH) * D_DIM;
        float* dst = xs + bufidx * (CH * XS);
        #pragma unroll
        for (int j = 0; j < 16; j++) {
            int i  = j * 256 + tid;
            int r  = i >> 6;
            int c4 = i & 63;
            uint32_t sa = (uint32_t)__cvta_generic_to_shared(dst + r * XS + c4 * 4);
            const float4* src = (const float4*)xg + (size_t)r * 64 + c4;
            asm volatile("cp.async.cg.shared.global [%0], [%1], 16;" :: "r"(sa), "l"(src));
        }
        asm volatile("cp.async.commit_group;");
    };

    int c0 = blockIdx.x;
    prefetch(c0, 0);

    int it = 0;
    for (int c = c0; c < NCHUNK; c += GRID, it++) {
        const int nb = it & 1;
        const int cn = c + GRID;
        if (cn < NCHUNK) {
            prefetch(cn, nb ^ 1);
            asm volatile("cp.async.wait_group 1;" ::: "memory");
        } else {
            asm volatile("cp.async.wait_group 0;" ::: "memory");
        }
        __syncthreads();   // buffer nb data visible to all; also orders last
                           // iteration's p0/p1/es consumers before re-writes below

        const float* cur = xs + nb * (CH * XS);
        const int b = c >> 6;

        // ---- Phase 2: fp16 MMA; warps 0-3 cols 0-31 (4 tiles), warps 4-7 cols 32-55 (3 tiles)
        if (warp < 4) phase2<4>(cur, Wh, us, bs, p0, mrow, 0,  g, t);
        else          phase2<3>(cur, Wh, us, bs, p1, mrow, 32, g, t);
        __syncthreads();

        // ---- exp + denominator (warp 0) ----
        if (warp == 0) {
            float e0 = __expf(p0[lane]      + p1[lane]);
            float e1 = __expf(p0[lane + 32] + p1[lane + 32]);
            es[lane]      = e0;
            es[lane + 32] = e1;
            float s = e0 + e1;
            #pragma unroll
            for (int o = 16; o > 0; o >>= 1) s += __shfl_xor_sync(0xFFFFFFFFu, s, o);
            if (lane == 0) atomicAdd(&g_denom[b], s);
        }
        __syncthreads();

        // ---- Phase 3: weighted sum over 64 rows; exact fp32 x from GLOBAL (L2-hot).
        //      Reads no SMEM x => next iteration's prefetch into buf nb cannot race
        //      phase 3, so no trailing barrier is needed.
        {
            const float* xg = x + ((size_t)b * T_LEN + (size_t)(c & 63) * CH) * D_DIM;
            float q0 = 0.f, q1 = 0.f, q2 = 0.f, q3 = 0.f;
            #pragma unroll 8
            for (int r = 0; r < CH; r += 4) {
                q0 += es[r + 0] * xg[(size_t)(r + 0) * D_DIM + tid];
                q1 += es[r + 1] * xg[(size_t)(r + 1) * D_DIM + tid];
                q2 += es[r + 2] * xg[(size_t)(r + 2) * D_DIM + tid];
                q3 += es[r + 3] * xg[(size_t)(r + 3) * D_DIM + tid];
            }
            atomicAdd(&out[b * D_DIM + tid], (q0 + q1) + (q2 + q3));
        }
        // (no trailing __syncthreads)
    }
}

__global__ void norm_kernel(float* __restrict__ out) {
    int i = blockIdx.x * blockDim.x + threadIdx.x;
    if (i < NBATCH * D_DIM) {
        out[i] = out[i] / (g_denom[i >> 8] + EPS);
    }
}

extern "C" void kernel_launch(void* const* d_in, const int* in_sizes, int n_in,
                              void* d_out, int out_size) {
    const float* x = (const float*)d_in[0];
    const float* W = (const float*)d_in[1];
    const float* b = (const float*)d_in[2];
    const float* u = (const float*)d_in[3];
    float* out = (float*)d_out;

    const int smem_bytes = (2 * CH * XS) * 4 + (128 * WS2) * 4 + (2 * NPAD + 3 * CH) * 4;
    cudaFuncSetAttribute(att_main_kernel,
                         cudaFuncAttributeMaxDynamicSharedMemorySize, smem_bytes);

    prep_kernel<<<(NBATCH * D_DIM + 255) / 256, 256>>>(W, b, u, out);
    att_main_kernel<<<GRID, 256, smem_bytes>>>(x, out);
    norm_kernel<<<(NBATCH * D_DIM + 255) / 256, 256>>>(out);
}

// round 13
// speedup vs baseline: 1.1565x; 1.1565x over previous
#include <cuda_runtime.h>
#include <cuda_fp16.h>
#include <cstdint>

#define T_LEN   4096
#define D_DIM   256
#define ATT     50
#define NPAD    64
#define CH      64      // rows per chunk
#define XS      264     // x row stride (floats): conflict-free LDS A loads & phase-3 reads
#define WS2     72      // W half2 row stride: conflict-free B loads
#define NBATCH  64
#define NCHUNK  (NBATCH * (T_LEN / CH))   // 4096
#define GRID    152     // GB300: 152 SMs, one wave at 1 CTA/SM
#define EPS     1e-7f

__device__ float   g_denom[NBATCH];
__device__ __half2 g_Wh2[128 * WS2];   // fp16 W^T pairs along k, zero-padded n>=ATT
__device__ float   g_up[NPAD];
__device__ float   g_bp[NPAD];

__device__ __forceinline__ float tanh_fast(float v) {
    float r;
    asm("tanh.approx.f32 %0, %1;" : "=f"(r) : "f"(v));
    return r;
}
__device__ __forceinline__ uint32_t h2u(__half2 h) {
    return *reinterpret_cast<uint32_t*>(&h);
}

__global__ void prep_kernel(const float* __restrict__ W,
                            const float* __restrict__ b,
                            const float* __restrict__ u,
                            float* __restrict__ out) {
    int i = blockIdx.x * blockDim.x + threadIdx.x;
    if (i < 128 * 64) {
        int k2 = i >> 6, n = i & 63;
        float w0 = (n < ATT) ? W[(2 * k2)     * ATT + n] : 0.0f;
        float w1 = (n < ATT) ? W[(2 * k2 + 1) * ATT + n] : 0.0f;
        g_Wh2[k2 * WS2 + n] = __floats2half2_rn(w0, w1);
    }
    if (i < NPAD) {
        g_up[i] = (i < ATT) ? u[i] : 0.0f;
        g_bp[i] = (i < ATT) ? b[i] : 0.0f;
    }
    if (i < NBATCH) g_denom[i] = 0.0f;
    if (i < NBATCH * D_DIM) out[i] = 0.0f;
}

// Phase-2 worker: NT n-tiles starting at column cbase. (R5 math; k-loop fully unrolled)
template<int NT>
__device__ __forceinline__ void phase2(const float* __restrict__ cur,
                                       const __half2* __restrict__ Wh,
                                       const float* __restrict__ us,
                                       const float* __restrict__ bs,
                                       float* __restrict__ pp,
                                       int mrow, int cbase, int g, int t) {
    float c[NT][4];
    #pragma unroll
    for (int nt = 0; nt < NT; nt++) {
        c[nt][0] = 0.f; c[nt][1] = 0.f; c[nt][2] = 0.f; c[nt][3] = 0.f;
    }
    const float* xr0 = cur + (mrow + g) * XS;
    const float* xr1 = xr0 + 8 * XS;

    #pragma unroll
    for (int k0 = 0; k0 < D_DIM; k0 += 16) {
        float2 f0 = *(const float2*)&xr0[k0 + 2 * t];
        float2 f1 = *(const float2*)&xr1[k0 + 2 * t];
        float2 f2 = *(const float2*)&xr0[k0 + 2 * t + 8];
        float2 f3 = *(const float2*)&xr1[k0 + 2 * t + 8];
        uint32_t a0 = h2u(__floats2half2_rn(f0.x, f0.y));
        uint32_t a1 = h2u(__floats2half2_rn(f1.x, f1.y));
        uint32_t a2 = h2u(__floats2half2_rn(f2.x, f2.y));
        uint32_t a3 = h2u(__floats2half2_rn(f3.x, f3.y));
        const __half2* wk0 = Wh + ((k0 >> 1) + t) * WS2 + cbase;
        const __half2* wk1 = wk0 + 4 * WS2;
        #pragma unroll
        for (int nt = 0; nt < NT; nt++) {
            uint32_t b0 = h2u(wk0[nt * 8 + g]);
            uint32_t b1 = h2u(wk1[nt * 8 + g]);
            asm volatile(
                "mma.sync.aligned.m16n8k16.row.col.f32.f16.f16.f32 "
                "{%0,%1,%2,%3}, {%4,%5,%6,%7}, {%8,%9}, {%0,%1,%2,%3};"
                : "+f"(c[nt][0]), "+f"(c[nt][1]), "+f"(c[nt][2]), "+f"(c[nt][3])
                : "r"(a0), "r"(a1), "r"(a2), "r"(a3), "r"(b0), "r"(b1));
        }
    }

    float slo = 0.f, shi = 0.f;
    #pragma unroll
    for (int nt = 0; nt < NT; nt++) {
        int col = cbase + nt * 8 + 2 * t;
        float u0 = us[col], u1 = us[col + 1];
        float B0 = bs[col], B1 = bs[col + 1];
        slo += tanh_fast(c[nt][0] + B0) * u0 + tanh_fast(c[nt][1] + B1) * u1;
        shi += tanh_fast(c[nt][2] + B0) * u0 + tanh_fast(c[nt][3] + B1) * u1;
    }
    slo += __shfl_xor_sync(0xFFFFFFFFu, slo, 1);
    slo += __shfl_xor_sync(0xFFFFFFFFu, slo, 2);
    shi += __shfl_xor_sync(0xFFFFFFFFu, shi, 1);
    shi += __shfl_xor_sync(0xFFFFFFFFu, shi, 2);
    if (t == 0) {
        pp[mrow + g]     = slo;
        pp[mrow + g + 8] = shi;
    }
}

__global__ __launch_bounds__(256, 1)
void att_main_kernel(const float* __restrict__ x, float* __restrict__ out) {
    extern __shared__ float sm[];
    float*   xs  = sm;                              // 2 * CH * XS floats
    __half2* Wh  = (__half2*)(sm + 2 * CH * XS);    // 128 * WS2 half2
    float*   us  = (float*)(Wh + 128 * WS2);        // NPAD
    float*   bs  = us + NPAD;                       // NPAD
    float*   es  = bs + NPAD;                       // CH
    float*   p0  = es + CH;                         // CH
    float*   p1  = p0 + CH;                         // CH

    const int tid = threadIdx.x;

    // ---- Stage fp16 W + vectors (once per CTA) ----
    #pragma unroll
    for (int i = tid; i < 128 * WS2 / 4; i += 256)
        ((float4*)Wh)[i] = ((const float4*)g_Wh2)[i];
    if (tid < NPAD) { us[tid] = g_up[tid]; bs[tid] = g_bp[tid]; }

    const int lane = tid & 31;
    const int warp = tid >> 5;
    const int g = lane >> 2;
    const int t = lane & 3;
    const int mrow = (warp & 3) * 16;

    auto prefetch = [&](int c, int bufidx) {
        const float* xg = x + ((size_t)(c >> 6) * T_LEN + (size_t)(c & 63) * CH) * D_DIM;
        float* dst = xs + bufidx * (CH * XS);
        #pragma unroll
        for (int j = 0; j < 16; j++) {
            int i  = j * 256 + tid;
            int r  = i >> 6;
            int c4 = i & 63;
            uint32_t sa = (uint32_t)__cvta_generic_to_shared(dst + r * XS + c4 * 4);
            const float4* src = (const float4*)xg + (size_t)r * 64 + c4;
            asm volatile("cp.async.cg.shared.global [%0], [%1], 16;" :: "r"(sa), "l"(src));
        }
        asm volatile("cp.async.commit_group;");
    };

    int c0 = blockIdx.x;
    prefetch(c0, 0);

    int it = 0;
    for (int c = c0; c < NCHUNK; c += GRID, it++) {
        const int nb = it & 1;
        const int cn = c + GRID;
        if (cn < NCHUNK) {
            prefetch(cn, nb ^ 1);
            asm volatile("cp.async.wait_group 1;" ::: "memory");
        } else {
            asm volatile("cp.async.wait_group 0;" ::: "memory");
        }
        __syncthreads();

        const float* cur = xs + nb * (CH * XS);
        const int b = c >> 6;

        // ---- Phase 2: fp16 MMA; warps 0-3 cols 0-31 (4 tiles), warps 4-7 cols 32-55 (3 tiles)
        if (warp < 4) phase2<4>(cur, Wh, us, bs, p0, mrow, 0,  g, t);
        else          phase2<3>(cur, Wh, us, bs, p1, mrow, 32, g, t);
        __syncthreads();

        // ---- exp + denominator (warp 0) ----
        if (warp == 0) {
            float e0 = __expf(p0[lane]      + p1[lane]);
            float e1 = __expf(p0[lane + 32] + p1[lane + 32]);
            es[lane]      = e0;
            es[lane + 32] = e1;
            float s = e0 + e1;
            #pragma unroll
            for (int o = 16; o > 0; o >>= 1) s += __shfl_xor_sync(0xFFFFFFFFu, s, o);
            if (lane == 0) atomicAdd(&g_denom[b], s);
        }
        __syncthreads();

        // ---- Phase 3: weighted sum over rows; 256 threads = 128 col-pairs x 2 row-halves
        //      float2 loads: half the LDS issue count of the scalar version.
        {
            const int cp   = tid & 127;           // column pair: cols 2cp, 2cp+1
            const int rbeg = (tid >> 7) * 32;     // row half: 0 or 32
            const float* base = cur + 2 * cp;
            float q0 = 0.f, q1 = 0.f, q2 = 0.f, q3 = 0.f;
            #pragma unroll 8
            for (int r = rbeg; r < rbeg + 32; r += 2) {
                float2 v0 = *(const float2*)&base[(r + 0) * XS];
                float2 v1 = *(const float2*)&base[(r + 1) * XS];
                q0 += es[r + 0] * v0.x;
                q1 += es[r + 0] * v0.y;
                q2 += es[r + 1] * v1.x;
                q3 += es[r + 1] * v1.y;
            }
            atomicAdd(&out[b * D_DIM + 2 * cp],     q0 + q2);
            atomicAdd(&out[b * D_DIM + 2 * cp + 1], q1 + q3);
        }

        __syncthreads();  // buffer + es/p reuse before next prefetch
    }
}

__global__ void norm_kernel(float* __restrict__ out) {
    int i = blockIdx.x * blockDim.x + threadIdx.x;
    if (i < NBATCH * D_DIM) {
        out[i] = out[i] / (g_denom[i >> 8] + EPS);
    }
}

extern "C" void kernel_launch(void* const* d_in, const int* in_sizes, int n_in,
                              void* d_out, int out_size) {
    const float* x = (const float*)d_in[0];
    const float* W = (const float*)d_in[1];
    const float* b = (const float*)d_in[2];
    const float* u = (const float*)d_in[3];
    float* out = (float*)d_out;

    const int smem_bytes = (2 * CH * XS) * 4 + (128 * WS2) * 4 + (2 * NPAD + 3 * CH) * 4;
    cudaFuncSetAttribute(att_main_kernel,
                         cudaFuncAttributeMaxDynamicSharedMemorySize, smem_bytes);

    prep_kernel<<<(NBATCH * D_DIM + 255) / 256, 256>>>(W, b, u, out);
    att_main_kernel<<<GRID, 256, smem_bytes>>>(x, out);
    norm_kernel<<<(NBATCH * D_DIM + 255) / 256, 256>>>(out);
}

// round 14
// speedup vs baseline: 1.1895x; 1.0286x over previous
#include <cuda_runtime.h>
#include <cuda_fp16.h>
#include <cstdint>

#define T_LEN   4096
#define D_DIM   256
#define ATT     50
#define NPAD    64
#define CH      64      // rows per chunk
#define XS      264     // x row stride (floats): conflict-free LDS.64 A loads & phase-3 reads
#define WS2     72      // W half2 row stride: conflict-free B loads
#define NBATCH  64
#define NCHUNK  (NBATCH * (T_LEN / CH))   // 4096
#define GRID    152     // GB300: 152 SMs, one wave at 1 CTA/SM
#define EPS     1e-7f

__device__ float   g_denom[NBATCH];
__device__ __half2 g_Wh2[128 * WS2];   // fp16 W^T pairs along k, zero-padded n>=ATT
__device__ float   g_up[NPAD];
__device__ float   g_bp[NPAD];

__device__ __forceinline__ float tanh_fast(float v) {
    float r;
    asm("tanh.approx.f32 %0, %1;" : "=f"(r) : "f"(v));
    return r;
}
__device__ __forceinline__ uint32_t h2u(__half2 h) {
    return *reinterpret_cast<uint32_t*>(&h);
}

__global__ void prep_kernel(const float* __restrict__ W,
                            const float* __restrict__ b,
                            const float* __restrict__ u,
                            float* __restrict__ out) {
    int i = blockIdx.x * blockDim.x + threadIdx.x;
    if (i < 128 * 64) {
        int k2 = i >> 6, n = i & 63;
        float w0 = (n < ATT) ? W[(2 * k2)     * ATT + n] : 0.0f;
        float w1 = (n < ATT) ? W[(2 * k2 + 1) * ATT + n] : 0.0f;
        g_Wh2[k2 * WS2 + n] = __floats2half2_rn(w0, w1);
    }
    if (i < NPAD) {
        g_up[i] = (i < ATT) ? u[i] : 0.0f;
        g_bp[i] = (i < ATT) ? b[i] : 0.0f;
    }
    if (i < NBATCH) g_denom[i] = 0.0f;
    if (i < NBATCH * D_DIM) out[i] = 0.0f;
}

// Phase-2 worker: NT n-tiles starting at column cbase. (identical to the 76.3us kernel)
template<int NT>
__device__ __forceinline__ void phase2(const float* __restrict__ cur,
                                       const __half2* __restrict__ Wh,
                                       const float* __restrict__ us,
                                       const float* __restrict__ bs,
                                       float* __restrict__ pp,
                                       int mrow, int cbase, int g, int t) {
    float c[NT][4];
    #pragma unroll
    for (int nt = 0; nt < NT; nt++) {
        c[nt][0] = 0.f; c[nt][1] = 0.f; c[nt][2] = 0.f; c[nt][3] = 0.f;
    }
    const float* xr0 = cur + (mrow + g) * XS;
    const float* xr1 = xr0 + 8 * XS;

    #pragma unroll 4
    for (int k0 = 0; k0 < D_DIM; k0 += 16) {
        float2 f0 = *(const float2*)&xr0[k0 + 2 * t];
        float2 f1 = *(const float2*)&xr1[k0 + 2 * t];
        float2 f2 = *(const float2*)&xr0[k0 + 2 * t + 8];
        float2 f3 = *(const float2*)&xr1[k0 + 2 * t + 8];
        uint32_t a0 = h2u(__floats2half2_rn(f0.x, f0.y));
        uint32_t a1 = h2u(__floats2half2_rn(f1.x, f1.y));
        uint32_t a2 = h2u(__floats2half2_rn(f2.x, f2.y));
        uint32_t a3 = h2u(__floats2half2_rn(f3.x, f3.y));
        const __half2* wk0 = Wh + ((k0 >> 1) + t) * WS2 + cbase;
        const __half2* wk1 = wk0 + 4 * WS2;
        #pragma unroll
        for (int nt = 0; nt < NT; nt++) {
            uint32_t b0 = h2u(wk0[nt * 8 + g]);
            uint32_t b1 = h2u(wk1[nt * 8 + g]);
            asm volatile(
                "mma.sync.aligned.m16n8k16.row.col.f32.f16.f16.f32 "
                "{%0,%1,%2,%3}, {%4,%5,%6,%7}, {%8,%9}, {%0,%1,%2,%3};"
                : "+f"(c[nt][0]), "+f"(c[nt][1]), "+f"(c[nt][2]), "+f"(c[nt][3])
                : "r"(a0), "r"(a1), "r"(a2), "r"(a3), "r"(b0), "r"(b1));
        }
    }

    float slo = 0.f, shi = 0.f;
    #pragma unroll
    for (int nt = 0; nt < NT; nt++) {
        int col = cbase + nt * 8 + 2 * t;
        float u0 = us[col], u1 = us[col + 1];
        float B0 = bs[col], B1 = bs[col + 1];
        slo += tanh_fast(c[nt][0] + B0) * u0 + tanh_fast(c[nt][1] + B1) * u1;
        shi += tanh_fast(c[nt][2] + B0) * u0 + tanh_fast(c[nt][3] + B1) * u1;
    }
    slo += __shfl_xor_sync(0xFFFFFFFFu, slo, 1);
    slo += __shfl_xor_sync(0xFFFFFFFFu, slo, 2);
    shi += __shfl_xor_sync(0xFFFFFFFFu, shi, 1);
    shi += __shfl_xor_sync(0xFFFFFFFFu, shi, 2);
    if (t == 0) {
        pp[mrow + g]     = slo;
        pp[mrow + g + 8] = shi;
    }
}

__global__ __launch_bounds__(256, 1)
void att_main_kernel(const float* __restrict__ x, float* __restrict__ out) {
    extern __shared__ float sm[];
    float*   xs  = sm;                              // 2 * CH * XS floats
    __half2* Wh  = (__half2*)(sm + 2 * CH * XS);    // 128 * WS2 half2
    float*   us  = (float*)(Wh + 128 * WS2);        // NPAD
    float*   bs  = us + NPAD;                       // NPAD
    float*   es  = bs + NPAD;                       // CH
    float*   p0  = es + CH;                         // CH
    float*   p1  = p0 + CH;                         // CH

    const int tid = threadIdx.x;

    // ---- Stage fp16 W + vectors (once per CTA) ----
    #pragma unroll
    for (int i = tid; i < 128 * WS2 / 4; i += 256)
        ((float4*)Wh)[i] = ((const float4*)g_Wh2)[i];
    if (tid < NPAD) { us[tid] = g_up[tid]; bs[tid] = g_bp[tid]; }

    const int lane = tid & 31;
    const int warp = tid >> 5;
    const int g = lane >> 2;
    const int t = lane & 3;
    const int mrow = (warp & 3) * 16;

    auto prefetch = [&](int c, int bufidx) {
        const float* xg = x + ((size_t)(c >> 6) * T_LEN + (size_t)(c & 63) * CH) * D_DIM;
        float* dst = xs + bufidx * (CH * XS);
        #pragma unroll
        for (int j = 0; j < 16; j++) {
            int i  = j * 256 + tid;
            int r  = i >> 6;
            int c4 = i & 63;
            uint32_t sa = (uint32_t)__cvta_generic_to_shared(dst + r * XS + c4 * 4);
            const float4* src = (const float4*)xg + (size_t)r * 64 + c4;
            asm volatile("cp.async.cg.shared.global [%0], [%1], 16;" :: "r"(sa), "l"(src));
        }
        asm volatile("cp.async.commit_group;");
    };

    int c0 = blockIdx.x;
    prefetch(c0, 0);

    int it = 0;
    for (int c = c0; c < NCHUNK; c += GRID, it++) {
        const int nb = it & 1;
        const int cn = c + GRID;
        if (cn < NCHUNK) {
            prefetch(cn, nb ^ 1);
            asm volatile("cp.async.wait_group 1;" ::: "memory");
        } else {
            asm volatile("cp.async.wait_group 0;" ::: "memory");
        }
        __syncthreads();   // buffer nb visible; also the reuse barrier for
                           // p0/p1/es from the previous iteration (all their
                           // readers -- exp and phase 3 -- finished before it)

        const float* cur = xs + nb * (CH * XS);
        const int b = c >> 6;

        // ---- Phase 2: fp16 MMA; warps 0-3 cols 0-31 (4 tiles), warps 4-7 cols 32-55 (3 tiles)
        if (warp < 4) phase2<4>(cur, Wh, us, bs, p0, mrow, 0,  g, t);
        else          phase2<3>(cur, Wh, us, bs, p1, mrow, 32, g, t);
        __syncthreads();

        // ---- exp + denominator: parallel across all 8 warps (8 rows each) ----
        {
            float e = 0.f;
            if (lane < 8) {
                int row = warp * 8 + lane;
                e = __expf(p0[row] + p1[row]);
                es[row] = e;
            }
            // warp-local sum of the 8 exps (lanes 8-31 contribute 0)
            #pragma unroll
            for (int o = 16; o > 0; o >>= 1) e += __shfl_xor_sync(0xFFFFFFFFu, e, o);
            if (lane == 0) atomicAdd(&g_denom[b], e);
        }
        __syncthreads();

        // ---- Phase 3: weighted sum over 64 rows, exact fp32 x (R5 scalar form) ----
        float q0 = 0.f, q1 = 0.f, q2 = 0.f, q3 = 0.f;
        #pragma unroll 16
        for (int r = 0; r < CH; r += 4) {
            q0 += es[r + 0] * cur[(r + 0) * XS + tid];
            q1 += es[r + 1] * cur[(r + 1) * XS + tid];
            q2 += es[r + 2] * cur[(r + 2) * XS + tid];
            q3 += es[r + 3] * cur[(r + 3) * XS + tid];
        }
        atomicAdd(&out[b * D_DIM + tid], (q0 + q1) + (q2 + q3));

        // (trailing __syncthreads removed: next prefetch writes buf nb^1, which
        //  phase 3 never touches; p0/p1/es rewrites happen only after the next
        //  iteration's post-wait_group barrier)
    }
}

__global__ void norm_kernel(float* __restrict__ out) {
    int i = blockIdx.x * blockDim.x + threadIdx.x;
    if (i < NBATCH * D_DIM) {
        out[i] = out[i] / (g_denom[i >> 8] + EPS);
    }
}

extern "C" void kernel_launch(void* const* d_in, const int* in_sizes, int n_in,
                              void* d_out, int out_size) {
    const float* x = (const float*)d_in[0];
    const float* W = (const float*)d_in[1];
    const float* b = (const float*)d_in[2];
    const float* u = (const float*)d_in[3];
    float* out = (float*)d_out;

    const int smem_bytes = (2 * CH * XS) * 4 + (128 * WS2) * 4 + (2 * NPAD + 3 * CH) * 4;
    cudaFuncSetAttribute(att_main_kernel,
                         cudaFuncAttributeMaxDynamicSharedMemorySize, smem_bytes);

    prep_kernel<<<(NBATCH * D_DIM + 255) / 256, 256>>>(W, b, u, out);
    att_main_kernel<<<GRID, 256, smem_bytes>>>(x, out);
    norm_kernel<<<(NBATCH * D_DIM + 255) / 256, 256>>>(out);
}